// round 2
// baseline (speedup 1.0000x reference)
#include <cuda_runtime.h>
#include <math.h>
#include <stdint.h>

// Problem constants
#define BATCH 512
#define C 3
#define NIMG 128
#define LNUM 3
#define H_ELEMS (BATCH * C * NIMG * NIMG)   // 25165824

// ---------------- device scratch (no allocations allowed) ----------------
__device__ __align__(16) float g_ecb[LNUM * C * NIMG * NIMG * 2]; // interleaved {exp(cls), conv_bias}
__device__ __align__(16) float g_Wp[LNUM * 3 * 3 * 12];           // folded conv weights, 12 floats per (o,in)
__device__ __align__(16) float g_aux[LNUM * 12];                  // per layer: B[3], alpha[3], 1/alpha[3], pad
__device__ float g_cls_part[576];
__device__ float g_kld_part[LNUM * 64];
__device__ float g_scalarS;
__device__ float g_scratch[BATCH * 16];

// =========================================================================
// P1: exp(conv_log_scale) interleave with conv_bias + partial sums of cls
// =========================================================================
__global__ void prep_ecb(const float* __restrict__ cls, const float* __restrict__ cbias) {
    __shared__ float sred[256];
    int idx = blockIdx.x * 256 + threadIdx.x;   // 576*256 = 147456 exactly
    float v = cls[idx];
    g_ecb[2 * idx]     = expf(v);
    g_ecb[2 * idx + 1] = cbias[idx];
    sred[threadIdx.x] = v;
    __syncthreads();
    for (int s = 128; s > 0; s >>= 1) {
        if (threadIdx.x < s) sred[threadIdx.x] += sred[threadIdx.x + s];
        __syncthreads();
    }
    if (threadIdx.x == 0) g_cls_part[blockIdx.x] = sred[0];
}

// =========================================================================
// P2: fold actnorm into conv weights; alpha tables
//   v' = a_in * v + b_in ;  conv(v') = sum (K*a_in) v + sum_in b_in*sum_t K
// Layout of g_Wp: index = ((l*3+o)*3+in)*12 + tap  ->  108 floats per layer.
// =========================================================================
__global__ void prep_w(const float* __restrict__ K, const float* __restrict__ als,
                       const float* __restrict__ ab, const float* __restrict__ sla) {
    int t = threadIdx.x;
    // folded weights (324 floats total: 3 layers * 108)
    for (int i = t; i < LNUM * 108; i += 256) {
        int l = i / 108, r = i % 108;
        int o = r / 36, r2 = r % 36;
        int in = r2 / 12, tap = r2 % 12;
        float val = 0.f;
        if (tap < 9) {
            float a = expf(als[l * 3 + in]);
            val = K[((l * 3 + o) * 3 + in) * 9 + tap] * a;
        }
        g_Wp[i] = val;
    }
    // aux (36 floats)
    for (int i = t; i < LNUM * 12; i += 256) {
        int l = i / 12, j = i % 12;
        float val = 0.f;
        if (j < 3) {  // B[o] = sum_in b_in * sum_tap K[o][in][tap]
            float s = 0.f;
            for (int in = 0; in < 3; in++) {
                float ks = 0.f;
                for (int tap = 0; tap < 9; tap++)
                    ks += K[((l * 3 + j) * 3 + in) * 9 + tap];
                s += ab[l * 3 + in] * ks;
            }
            val = s;
        } else if (j < 6) {
            val = expf(sla[l * 3 + (j - 3)]);
        } else if (j < 9) {
            val = 1.0f / expf(sla[l * 3 + (j - 6)]);
        }
        g_aux[i] = val;
    }
}

// =========================================================================
// P3: spectral log|det| of circular conv operator.
//   M(u,v)[a][b] = sum_{p,q} K[a,b,p,q] e^{-2pi i (u p + v q)/128};  sum log|det M|
// =========================================================================
__global__ void kld_kernel(const float* __restrict__ K) {
    __shared__ float2 tw[128];
    __shared__ float sK[LNUM * 81];
    __shared__ float sred[256];
    int tid = threadIdx.x;
    if (tid < 128) {
        double a = -2.0 * 3.14159265358979323846 * (double)tid / 128.0;
        double s, c; sincos(a, &s, &c);
        tw[tid] = make_float2((float)c, (float)s);
    }
    if (tid < LNUM * 81) sK[tid] = K[tid];
    __syncthreads();

    int point = blockIdx.x * 256 + tid;  // 64*256 = 16384
    int u = point >> 7, v = point & 127;

    float res[LNUM];
    #pragma unroll
    for (int l = 0; l < LNUM; l++) {
        float er[9], ei[9];
        #pragma unroll
        for (int p = 0; p < 3; p++)
            #pragma unroll
            for (int q = 0; q < 3; q++) {
                int m = (u * p + v * q) & 127;
                float2 t = tw[m];
                er[p * 3 + q] = t.x; ei[p * 3 + q] = t.y;
            }
        float mr[3][3], mi[3][3];
        #pragma unroll
        for (int a = 0; a < 3; a++)
            #pragma unroll
            for (int b = 0; b < 3; b++) {
                float rr = 0.f, ri = 0.f;
                #pragma unroll
                for (int t = 0; t < 9; t++) {
                    float kk = sK[l * 81 + (a * 3 + b) * 9 + t];
                    rr += kk * er[t]; ri += kk * ei[t];
                }
                mr[a][b] = rr; mi[a][b] = ri;
            }
        // 3x3 complex determinant, cofactor expansion along row 0
        float c0r = (mr[1][1]*mr[2][2] - mi[1][1]*mi[2][2]) - (mr[1][2]*mr[2][1] - mi[1][2]*mi[2][1]);
        float c0i = (mr[1][1]*mi[2][2] + mi[1][1]*mr[2][2]) - (mr[1][2]*mi[2][1] + mi[1][2]*mr[2][1]);
        float c1r = (mr[1][0]*mr[2][2] - mi[1][0]*mi[2][2]) - (mr[1][2]*mr[2][0] - mi[1][2]*mi[2][0]);
        float c1i = (mr[1][0]*mi[2][2] + mi[1][0]*mr[2][2]) - (mr[1][2]*mi[2][0] + mi[1][2]*mr[2][0]);
        float c2r = (mr[1][0]*mr[2][1] - mi[1][0]*mi[2][1]) - (mr[1][1]*mr[2][0] - mi[1][1]*mi[2][0]);
        float c2i = (mr[1][0]*mi[2][1] + mi[1][0]*mr[2][1]) - (mr[1][1]*mi[2][0] + mi[1][1]*mr[2][0]);
        float dr = (mr[0][0]*c0r - mi[0][0]*c0i) - (mr[0][1]*c1r - mi[0][1]*c1i) + (mr[0][2]*c2r - mi[0][2]*c2i);
        float di = (mr[0][0]*c0i + mi[0][0]*c0r) - (mr[0][1]*c1i + mi[0][1]*c1r) + (mr[0][2]*c2i + mi[0][2]*c2r);
        res[l] = 0.5f * logf(dr * dr + di * di);
    }

    for (int l = 0; l < LNUM; l++) {
        sred[tid] = res[l];
        __syncthreads();
        for (int s = 128; s > 0; s >>= 1) {
            if (tid < s) sred[tid] += sred[tid + s];
            __syncthreads();
        }
        if (tid == 0) g_kld_part[l * 64 + blockIdx.x] = sred[0];
        __syncthreads();
    }
}

// =========================================================================
// P4: assemble batch-independent scalar logdet
// =========================================================================
__global__ void finalize_scalar(const float* __restrict__ als) {
    __shared__ float sred[256];
    int t = threadIdx.x;
    float s = 0.f;
    for (int i = t; i < 576; i += 256) s += g_cls_part[i];
    for (int i = t; i < LNUM * 64; i += 256) s += g_kld_part[i];
    sred[t] = s;
    __syncthreads();
    for (int st = 128; st > 0; st >>= 1) {
        if (t < st) sred[t] += sred[t + st];
        __syncthreads();
    }
    if (t == 0) {
        float s2 = 0.f;
        for (int i = 0; i < 9; i++) s2 += als[i];
        g_scalarS = sred[0] + 16384.0f * s2;
    }
}

// =========================================================================
// Main fused kernel: 3 layers, 32x32 output tile, shrinking halos in smem.
// =========================================================================
template <int D, bool LAST>
__device__ __forceinline__ float stage_f(const float* __restrict__ sin_, int pin,
                                         float* __restrict__ sout, int pout,
                                         float* __restrict__ gout,
                                         int layer, int ty0, int tx0, int off, int tid) {
    // load folded weights (registers, float4 vectorized)
    float w[3][3][9];
    #pragma unroll
    for (int o = 0; o < 3; o++)
        #pragma unroll
        for (int in = 0; in < 3; in++) {
            const float4* p = (const float4*)&g_Wp[((layer * 3 + o) * 3 + in) * 12];
            float4 q0 = __ldg(p), q1 = __ldg(p + 1), q2 = __ldg(p + 2);
            w[o][in][0] = q0.x; w[o][in][1] = q0.y; w[o][in][2] = q0.z; w[o][in][3] = q0.w;
            w[o][in][4] = q1.x; w[o][in][5] = q1.y; w[o][in][6] = q1.z; w[o][in][7] = q1.w;
            w[o][in][8] = q2.x;
        }
    float4 a0 = __ldg((const float4*)&g_aux[layer * 12]);
    float4 a1 = __ldg((const float4*)&g_aux[layer * 12 + 4]);
    float4 a2 = __ldg((const float4*)&g_aux[layer * 12 + 8]);
    float Bf[3]  = {a0.x, a0.y, a0.z};
    float al[3]  = {a0.w, a1.x, a1.y};
    float ial[3] = {a1.z, a1.w, a2.x};

    const float* __restrict__ ecb = g_ecb + layer * (C * NIMG * NIMG * 2);
    float acc_ld = 0.f;
    const int DH = D / 2;

    for (int q = tid; q < DH * DH; q += 256) {
        int qy = q / DH, qx = q - qy * DH;
        int py = qy * 2, px = qx * 2;

        float acc[2][2][3];
        #pragma unroll
        for (int R = 0; R < 2; R++)
            #pragma unroll
            for (int Cc = 0; Cc < 2; Cc++)
                #pragma unroll
                for (int o = 0; o < 3; o++) acc[R][Cc][o] = Bf[o];

        #pragma unroll
        for (int in = 0; in < 3; in++) {
            const float* bp = sin_ + in * pin + py * 40 + px;
            float v[4][4];
            #pragma unroll
            for (int r = 0; r < 4; r++) {
                float2 u0 = *(const float2*)(bp + r * 40);
                float2 u1 = *(const float2*)(bp + r * 40 + 2);
                v[r][0] = u0.x; v[r][1] = u0.y; v[r][2] = u1.x; v[r][3] = u1.y;
            }
            #pragma unroll
            for (int o = 0; o < 3; o++)
                #pragma unroll
                for (int R = 0; R < 2; R++)
                    #pragma unroll
                    for (int ty = 0; ty < 3; ty++)
                        #pragma unroll
                        for (int tx = 0; tx < 3; tx++) {
                            float wk = w[o][in][ty * 3 + tx];
                            acc[R][0][o] = fmaf(wk, v[R + ty][tx], acc[R][0][o]);
                            acc[R][1][o] = fmaf(wk, v[R + ty][tx + 1], acc[R][1][o]);
                        }
        }

        // epilogue: exp(cls)*conv + bias -> slog -> store + logdet accum
        #pragma unroll
        for (int R = 0; R < 2; R++) {
            int yloc = py + R - off;
            int gy = (ty0 + yloc) & 127;
            #pragma unroll
            for (int o = 0; o < 3; o++) {
                float h2[2];
                #pragma unroll
                for (int Cc = 0; Cc < 2; Cc++) {
                    int xloc = px + Cc - off;
                    int gx = (tx0 + xloc) & 127;
                    float2 eb = *(const float2*)&ecb[((o * NIMG + gy) * NIMG + gx) * 2];
                    float u = fmaf(eb.x, acc[R][Cc][o], eb.y);
                    float au = fabsf(u);
                    float wv = ial[o] * __logf(fmaf(al[o], au, 1.0f));  // (1/a)*log1p(a|u|)
                    h2[Cc] = copysignf(wv, u);
                    bool inc = LAST || ((unsigned)yloc < 32u && (unsigned)xloc < 32u);
                    if (inc) acc_ld -= al[o] * wv;
                    if (!LAST) sout[o * pout + (py + R) * 40 + (px + Cc)] = h2[Cc];
                }
                if (LAST) {
                    *(float2*)(gout + ((size_t)o * NIMG + gy) * NIMG + (tx0 + px)) =
                        make_float2(h2[0], h2[1]);
                }
            }
        }
    }
    return acc_ld;
}

__global__ void __launch_bounds__(256) flow_main(const float* __restrict__ x,
                                                 float* __restrict__ out) {
    const int tid = threadIdx.x;
    const int tile = blockIdx.x;  // 0..15
    const int b = blockIdx.y;
    const int tx0 = (tile & 3) * 32;
    const int ty0 = (tile >> 2) * 32;

    __shared__ __align__(16) float sA[3 * 38 * 40];
    __shared__ __align__(16) float sB[3 * 36 * 40];
    __shared__ float sred[256];

    // Load raw input tile (38x38 with wrap halo of 3)
    const float* __restrict__ xb = x + (size_t)b * (C * NIMG * NIMG);
    for (int i = tid; i < 3 * 38 * 38; i += 256) {
        int c = i / (38 * 38);
        int rem = i - c * (38 * 38);
        int r = rem / 38;
        int col = rem - r * 38;
        int gy = (ty0 + r - 3) & 127;
        int gx = (tx0 + col - 3) & 127;
        sA[c * (38 * 40) + r * 40 + col] = xb[(c * NIMG + gy) * NIMG + gx];
    }
    __syncthreads();

    float ldacc = 0.f;
    // layer 0: in sA(38 rows), out sB(36 rows), off=2
    ldacc += stage_f<36, false>(sA, 38 * 40, sB, 36 * 40, nullptr, 0, ty0, tx0, 2, tid);
    __syncthreads();
    // layer 1: in sB(36 rows), out sA(34 rows), off=1
    ldacc += stage_f<34, false>(sB, 36 * 40, sA, 34 * 40, nullptr, 1, ty0, tx0, 1, tid);
    __syncthreads();
    // layer 2: in sA(34 rows), out gmem, off=0
    ldacc += stage_f<32, true>(sA, 34 * 40, nullptr, 0,
                               out + (size_t)b * (C * NIMG * NIMG), 2, ty0, tx0, 0, tid);

    // deterministic block reduction of slog-logdet partial
    sred[tid] = ldacc;
    __syncthreads();
    for (int s = 128; s > 0; s >>= 1) {
        if (tid < s) sred[tid] += sred[tid + s];
        __syncthreads();
    }
    if (tid == 0) g_scratch[b * 16 + tile] = sred[0];
}

// =========================================================================
// F: per-batch logdet = scalar part + 16 tile partials (deterministic order)
// =========================================================================
__global__ void final_ld(float* __restrict__ out) {
    int b = blockIdx.x * blockDim.x + threadIdx.x;
    if (b < BATCH) {
        float s = g_scalarS;
        #pragma unroll
        for (int t = 0; t < 16; t++) s += g_scratch[b * 16 + t];
        out[H_ELEMS + b] = s;
    }
}

// =========================================================================
extern "C" void kernel_launch(void* const* d_in, const int* in_sizes, int n_in,
                              void* d_out, int out_size) {
    const float* x     = (const float*)d_in[0];  // (512,3,128,128)
    const float* ab    = (const float*)d_in[1];  // actnorm_bias (3,1,3,1,1)
    const float* als   = (const float*)d_in[2];  // actnorm_log_scale
    const float* K     = (const float*)d_in[3];  // conv_kernel (3,3,3,3,3)
    const float* cbias = (const float*)d_in[4];  // conv_bias (3,1,3,128,128)
    const float* cls   = (const float*)d_in[5];  // conv_log_scale
    const float* sla   = (const float*)d_in[6];  // slog_log_alpha
    float* out = (float*)d_out;

    prep_ecb<<<576, 256>>>(cls, cbias);
    prep_w<<<1, 256>>>(K, als, ab, sla);
    kld_kernel<<<64, 256>>>(K);
    finalize_scalar<<<1, 256>>>(als);
    flow_main<<<dim3(16, BATCH), 256>>>(x, out);
    final_ld<<<2, 256>>>(out);
}

// round 3
// speedup vs baseline: 1.5216x; 1.5216x over previous
#include <cuda_runtime.h>
#include <math.h>
#include <stdint.h>

typedef unsigned long long ull;

// Problem constants
#define BATCH 512
#define C 3
#define NIMG 128
#define LNUM 3
#define H_ELEMS (BATCH * C * NIMG * NIMG)   // 25165824

// ---------------- device scratch (no allocations allowed) ----------------
__device__ __align__(16) float g_ecb[LNUM * C * NIMG * NIMG * 2]; // interleaved {exp(cls), conv_bias}
__device__ __align__(16) float g_Wp[LNUM * 3 * 3 * 12];           // folded conv weights, 12/(o,in)
__device__ __align__(16) float g_aux[LNUM * 12];                  // per layer: B[3], alpha[3], 1/alpha[3]
__device__ float g_cls_part[576];
__device__ float g_kld_part[LNUM * 64];
__device__ float g_scratch[BATCH * 16];

// ---------------- packed f32x2 helpers ----------------
__device__ __forceinline__ ull pk(float lo, float hi) {
    ull r; asm("mov.b64 %0,{%1,%2};" : "=l"(r) : "f"(lo), "f"(hi)); return r;
}
__device__ __forceinline__ void upk(ull p, float& lo, float& hi) {
    asm("mov.b64 {%0,%1},%2;" : "=f"(lo), "=f"(hi) : "l"(p));
}
__device__ __forceinline__ ull f2fma(ull a, ull b, ull c) {
    ull d; asm("fma.rn.f32x2 %0,%1,%2,%3;" : "=l"(d) : "l"(a), "l"(b), "l"(c)); return d;
}
// middle pair {hi(a), lo(b)}
__device__ __forceinline__ ull mkmid(ull a, ull b) {
    float alo, ahi, blo, bhi;
    asm("mov.b64 {%0,%1},%2;" : "=f"(alo), "=f"(ahi) : "l"(a));
    asm("mov.b64 {%0,%1},%2;" : "=f"(blo), "=f"(bhi) : "l"(b));
    ull m; asm("mov.b64 %0,{%1,%2};" : "=l"(m) : "f"(ahi), "f"(blo));
    return m;
}

// =========================================================================
// P1: exp(conv_log_scale) interleaved with conv_bias + partial sums of cls
// =========================================================================
__global__ void prep_ecb(const float* __restrict__ cls, const float* __restrict__ cbias) {
    __shared__ float sred[256];
    int idx = blockIdx.x * 256 + threadIdx.x;   // 576*256 = 147456 exactly
    float v = cls[idx];
    g_ecb[2 * idx]     = expf(v);
    g_ecb[2 * idx + 1] = cbias[idx];
    sred[threadIdx.x] = v;
    __syncthreads();
    for (int s = 128; s > 0; s >>= 1) {
        if (threadIdx.x < s) sred[threadIdx.x] += sred[threadIdx.x + s];
        __syncthreads();
    }
    if (threadIdx.x == 0) g_cls_part[blockIdx.x] = sred[0];
}

// =========================================================================
// P2: fold actnorm into conv weights; alpha tables
//   g_Wp layout: ((l*3+o)*3+in)*12 + tap  (108 floats per layer)
// =========================================================================
__global__ void prep_w(const float* __restrict__ K, const float* __restrict__ als,
                       const float* __restrict__ ab, const float* __restrict__ sla) {
    int t = threadIdx.x;
    for (int i = t; i < LNUM * 108; i += 256) {
        int l = i / 108, r = i % 108;
        int o = r / 36, r2 = r % 36;
        int in = r2 / 12, tap = r2 % 12;
        float val = 0.f;
        if (tap < 9) {
            float a = expf(als[l * 3 + in]);
            val = K[((l * 3 + o) * 3 + in) * 9 + tap] * a;
        }
        g_Wp[i] = val;
    }
    for (int i = t; i < LNUM * 12; i += 256) {
        int l = i / 12, j = i % 12;
        float val = 0.f;
        if (j < 3) {
            float s = 0.f;
            for (int in = 0; in < 3; in++) {
                float ks = 0.f;
                for (int tap = 0; tap < 9; tap++)
                    ks += K[((l * 3 + j) * 3 + in) * 9 + tap];
                s += ab[l * 3 + in] * ks;
            }
            val = s;
        } else if (j < 6) {
            val = expf(sla[l * 3 + (j - 3)]);
        } else if (j < 9) {
            val = 1.0f / expf(sla[l * 3 + (j - 6)]);
        }
        g_aux[i] = val;
    }
}

// =========================================================================
// P3: spectral log|det| of circular conv operator
// =========================================================================
__global__ void kld_kernel(const float* __restrict__ K) {
    __shared__ float2 tw[128];
    __shared__ float sK[LNUM * 81];
    __shared__ float sred[256];
    int tid = threadIdx.x;
    if (tid < 128) {
        double a = -2.0 * 3.14159265358979323846 * (double)tid / 128.0;
        double s, c; sincos(a, &s, &c);
        tw[tid] = make_float2((float)c, (float)s);
    }
    if (tid < LNUM * 81) sK[tid] = K[tid];
    __syncthreads();

    int point = blockIdx.x * 256 + tid;  // 64*256 = 16384
    int u = point >> 7, v = point & 127;

    float res[LNUM];
    #pragma unroll
    for (int l = 0; l < LNUM; l++) {
        float er[9], ei[9];
        #pragma unroll
        for (int p = 0; p < 3; p++)
            #pragma unroll
            for (int q = 0; q < 3; q++) {
                int m = (u * p + v * q) & 127;
                float2 t = tw[m];
                er[p * 3 + q] = t.x; ei[p * 3 + q] = t.y;
            }
        float mr[3][3], mi[3][3];
        #pragma unroll
        for (int a = 0; a < 3; a++)
            #pragma unroll
            for (int b = 0; b < 3; b++) {
                float rr = 0.f, ri = 0.f;
                #pragma unroll
                for (int t = 0; t < 9; t++) {
                    float kk = sK[l * 81 + (a * 3 + b) * 9 + t];
                    rr += kk * er[t]; ri += kk * ei[t];
                }
                mr[a][b] = rr; mi[a][b] = ri;
            }
        float c0r = (mr[1][1]*mr[2][2] - mi[1][1]*mi[2][2]) - (mr[1][2]*mr[2][1] - mi[1][2]*mi[2][1]);
        float c0i = (mr[1][1]*mi[2][2] + mi[1][1]*mr[2][2]) - (mr[1][2]*mi[2][1] + mi[1][2]*mr[2][1]);
        float c1r = (mr[1][0]*mr[2][2] - mi[1][0]*mi[2][2]) - (mr[1][2]*mr[2][0] - mi[1][2]*mi[2][0]);
        float c1i = (mr[1][0]*mi[2][2] + mi[1][0]*mr[2][2]) - (mr[1][2]*mi[2][0] + mi[1][2]*mr[2][0]);
        float c2r = (mr[1][0]*mr[2][1] - mi[1][0]*mi[2][1]) - (mr[1][1]*mr[2][0] - mi[1][1]*mi[2][0]);
        float c2i = (mr[1][0]*mi[2][1] + mi[1][0]*mr[2][1]) - (mr[1][1]*mi[2][0] + mi[1][1]*mr[2][0]);
        float dr = (mr[0][0]*c0r - mi[0][0]*c0i) - (mr[0][1]*c1r - mi[0][1]*c1i) + (mr[0][2]*c2r - mi[0][2]*c2i);
        float di = (mr[0][0]*c0i + mi[0][0]*c0r) - (mr[0][1]*c1i + mi[0][1]*c1r) + (mr[0][2]*c2i + mi[0][2]*c2r);
        res[l] = 0.5f * logf(dr * dr + di * di);
    }

    for (int l = 0; l < LNUM; l++) {
        sred[tid] = res[l];
        __syncthreads();
        for (int s = 128; s > 0; s >>= 1) {
            if (tid < s) sred[tid] += sred[tid + s];
            __syncthreads();
        }
        if (tid == 0) g_kld_part[l * 64 + blockIdx.x] = sred[0];
        __syncthreads();
    }
}

// =========================================================================
// Main fused kernel: 3 layers, 32x32 tile, shrinking halos, packed f32x2.
// =========================================================================
template <int D, bool LAST>
__device__ __forceinline__ float stage_p(const float* __restrict__ sin_, int pin,
                                         float* __restrict__ sout, int pout,
                                         float* __restrict__ gout,
                                         const ull* __restrict__ sWl,
                                         int layer, int ty0, int tx0, int off, int tid) {
    float4 a0 = __ldg((const float4*)&g_aux[layer * 12]);
    float4 a1 = __ldg((const float4*)&g_aux[layer * 12 + 4]);
    float4 a2 = __ldg((const float4*)&g_aux[layer * 12 + 8]);
    const float Bf[3]  = {a0.x, a0.y, a0.z};
    const float al[3]  = {a0.w, a1.x, a1.y};
    const float ial[3] = {a1.z, a1.w, a2.x};
    ull Bp[3];
    #pragma unroll
    for (int o = 0; o < 3; o++) Bp[o] = pk(Bf[o], Bf[o]);

    const float* __restrict__ ecb = g_ecb + layer * (C * NIMG * NIMG * 2);
    float acc_ld = 0.f;
    const int DH = D / 2;

    for (int q = tid; q < DH * DH; q += 256) {
        int qy = q / DH, qx = q - qy * DH;
        int py = qy * 2, px = qx * 2;

        ull acc2[2][3];
        #pragma unroll
        for (int R = 0; R < 2; R++)
            #pragma unroll
            for (int o = 0; o < 3; o++) acc2[R][o] = Bp[o];

        #pragma unroll
        for (int in = 0; in < 3; in++) {
            const float* bp = sin_ + in * pin + py * 40 + px;
            ull A[4], Bv[4], M[4];
            #pragma unroll
            for (int r = 0; r < 4; r++) {
                A[r]  = *(const ull*)(bp + r * 40);
                Bv[r] = *(const ull*)(bp + r * 40 + 2);
                M[r]  = mkmid(A[r], Bv[r]);
            }
            #pragma unroll
            for (int o = 0; o < 3; o++) {
                const ulonglong2* wb = (const ulonglong2*)(sWl + (in * 3 + o) * 10);
                ulonglong2 w01 = wb[0], w23 = wb[1], w45 = wb[2], w67 = wb[3], w8x = wb[4];
                ull wp[9] = {w01.x, w01.y, w23.x, w23.y, w45.x, w45.y, w67.x, w67.y, w8x.x};
                #pragma unroll
                for (int ty = 0; ty < 3; ty++) {
                    acc2[0][o] = f2fma(wp[ty * 3 + 0], A[ty],      acc2[0][o]);
                    acc2[0][o] = f2fma(wp[ty * 3 + 1], M[ty],      acc2[0][o]);
                    acc2[0][o] = f2fma(wp[ty * 3 + 2], Bv[ty],     acc2[0][o]);
                    acc2[1][o] = f2fma(wp[ty * 3 + 0], A[ty + 1],  acc2[1][o]);
                    acc2[1][o] = f2fma(wp[ty * 3 + 1], M[ty + 1],  acc2[1][o]);
                    acc2[1][o] = f2fma(wp[ty * 3 + 2], Bv[ty + 1], acc2[1][o]);
                }
            }
        }

        // epilogue: exp(cls)*conv + bias -> slog -> store + logdet accum
        #pragma unroll
        for (int R = 0; R < 2; R++) {
            int yloc = py + R - off;
            int gy = (ty0 + yloc) & 127;
            #pragma unroll
            for (int o = 0; o < 3; o++) {
                float c0, c1; upk(acc2[R][o], c0, c1);
                int xl0 = px - off;
                int gx0 = (tx0 + xl0) & 127;
                int gx1 = (tx0 + xl0 + 1) & 127;
                float2 e0 = *(const float2*)&ecb[((o * NIMG + gy) * NIMG + gx0) * 2];
                float2 e1 = *(const float2*)&ecb[((o * NIMG + gy) * NIMG + gx1) * 2];
                float u0 = fmaf(e0.x, c0, e0.y);
                float u1 = fmaf(e1.x, c1, e1.y);
                float w0 = ial[o] * __logf(fmaf(al[o], fabsf(u0), 1.0f));
                float w1 = ial[o] * __logf(fmaf(al[o], fabsf(u1), 1.0f));
                float h0 = copysignf(w0, u0);
                float h1 = copysignf(w1, u1);
                if (LAST || ((unsigned)yloc < 32u && (unsigned)xl0 < 32u))       acc_ld -= al[o] * w0;
                if (LAST || ((unsigned)yloc < 32u && (unsigned)(xl0 + 1) < 32u)) acc_ld -= al[o] * w1;
                if (!LAST) {
                    *(ull*)&sout[o * pout + (py + R) * 40 + px] = pk(h0, h1);
                } else {
                    *(float2*)(gout + ((size_t)o * NIMG + gy) * NIMG + (tx0 + px)) =
                        make_float2(h0, h1);
                }
            }
        }
    }
    return acc_ld;
}

__global__ void __launch_bounds__(256, 2) flow_main(const float* __restrict__ x,
                                                    float* __restrict__ out) {
    const int tid = threadIdx.x;
    const int b = blockIdx.x;        // batch-major for ecb locality
    const int tile = blockIdx.y;     // 0..15
    const int tx0 = (tile & 3) * 32;
    const int ty0 = (tile >> 2) * 32;

    __shared__ __align__(16) float sA[3 * 38 * 40];
    __shared__ __align__(16) float sB[3 * 36 * 40];
    __shared__ __align__(16) ull sW[LNUM * 90];   // [l][in][o][10] duplicated pairs
    __shared__ float sred[256];

    // Build packed weight table
    for (int i = tid; i < LNUM * 90; i += 256) {
        int l = i / 90, r = i % 90;
        int in = r / 30, r2 = r % 30;
        int o = r2 / 10, tap = r2 % 10;
        float v = (tap < 9) ? g_Wp[((l * 3 + o) * 3 + in) * 12 + tap] : 0.f;
        sW[i] = pk(v, v);
    }

    // Load raw input tile (38x38 with wrap halo of 3)
    const float* __restrict__ xb = x + (size_t)b * (C * NIMG * NIMG);
    for (int i = tid; i < 3 * 38 * 38; i += 256) {
        int c = i / (38 * 38);
        int rem = i - c * (38 * 38);
        int r = rem / 38;
        int col = rem - r * 38;
        int gy = (ty0 + r - 3) & 127;
        int gx = (tx0 + col - 3) & 127;
        sA[c * (38 * 40) + r * 40 + col] = xb[(c * NIMG + gy) * NIMG + gx];
    }
    __syncthreads();

    float ldacc = 0.f;
    ldacc += stage_p<36, false>(sA, 38 * 40, sB, 36 * 40, nullptr, sW + 0 * 90, 0, ty0, tx0, 2, tid);
    __syncthreads();
    ldacc += stage_p<34, false>(sB, 36 * 40, sA, 34 * 40, nullptr, sW + 1 * 90, 1, ty0, tx0, 1, tid);
    __syncthreads();
    ldacc += stage_p<32, true>(sA, 34 * 40, nullptr, 0,
                               out + (size_t)b * (C * NIMG * NIMG), sW + 2 * 90, 2, ty0, tx0, 0, tid);

    sred[tid] = ldacc;
    __syncthreads();
    for (int s = 128; s > 0; s >>= 1) {
        if (tid < s) sred[tid] += sred[tid + s];
        __syncthreads();
    }
    if (tid == 0) g_scratch[b * 16 + tile] = sred[0];
}

// =========================================================================
// F: per-batch logdet = scalar part + 16 tile partials (deterministic)
// =========================================================================
__global__ void final_ld(const float* __restrict__ als, float* __restrict__ out) {
    __shared__ float sred[256];
    int tid = threadIdx.x;
    float loc = 0.f;
    for (int i = tid; i < 576; i += 256) loc += g_cls_part[i];
    for (int i = tid; i < LNUM * 64; i += 256) loc += g_kld_part[i];
    sred[tid] = loc;
    __syncthreads();
    for (int s = 128; s > 0; s >>= 1) {
        if (tid < s) sred[tid] += sred[tid + s];
        __syncthreads();
    }
    if (tid == 0) {
        float s2 = 0.f;
        for (int i = 0; i < 9; i++) s2 += als[i];
        sred[0] = sred[0] + 16384.0f * s2;
    }
    __syncthreads();
    float scal = sred[0];
    int b = blockIdx.x * 256 + tid;
    if (b < BATCH) {
        float s = scal;
        #pragma unroll
        for (int t = 0; t < 16; t++) s += g_scratch[b * 16 + t];
        out[H_ELEMS + b] = s;
    }
}

// =========================================================================
extern "C" void kernel_launch(void* const* d_in, const int* in_sizes, int n_in,
                              void* d_out, int out_size) {
    const float* x     = (const float*)d_in[0];  // (512,3,128,128)
    const float* ab    = (const float*)d_in[1];  // actnorm_bias
    const float* als   = (const float*)d_in[2];  // actnorm_log_scale
    const float* K     = (const float*)d_in[3];  // conv_kernel
    const float* cbias = (const float*)d_in[4];  // conv_bias
    const float* cls   = (const float*)d_in[5];  // conv_log_scale
    const float* sla   = (const float*)d_in[6];  // slog_log_alpha
    float* out = (float*)d_out;

    prep_ecb<<<576, 256>>>(cls, cbias);
    prep_w<<<1, 256>>>(K, als, ab, sla);
    kld_kernel<<<64, 256>>>(K);
    flow_main<<<dim3(BATCH, 16), 256>>>(x, out);   // our launch #4 (ncu target)
    final_ld<<<2, 256>>>(als, out);
}

// round 4
// speedup vs baseline: 1.5540x; 1.0213x over previous
#include <cuda_runtime.h>
#include <math.h>
#include <stdint.h>

typedef unsigned long long ull;

// Problem constants
#define BATCH 512
#define C 3
#define NIMG 128
#define LNUM 3
#define H_ELEMS (BATCH * C * NIMG * NIMG)   // 25165824
#define TILES 32                            // 4 x-tiles (32 wide) x 8 y-tiles (16 tall)

// ---------------- device scratch (no allocations allowed) ----------------
__device__ __align__(16) float g_ecb[LNUM * C * NIMG * NIMG * 2]; // interleaved {exp(cls), conv_bias}
__device__ __align__(16) float g_Wp[LNUM * 3 * 3 * 12];           // folded conv weights, 12/(o,in)
__device__ __align__(16) float g_aux[LNUM * 12];                  // per layer: B[3], alpha[3], 1/alpha[3]
__device__ float g_cls_part[576];
__device__ float g_kld_part[LNUM * 64];
__device__ float g_scratch[BATCH * TILES];

// ---------------- packed f32x2 helpers ----------------
__device__ __forceinline__ ull pk(float lo, float hi) {
    ull r; asm("mov.b64 %0,{%1,%2};" : "=l"(r) : "f"(lo), "f"(hi)); return r;
}
__device__ __forceinline__ void upk(ull p, float& lo, float& hi) {
    asm("mov.b64 {%0,%1},%2;" : "=f"(lo), "=f"(hi) : "l"(p));
}
__device__ __forceinline__ ull f2fma(ull a, ull b, ull c) {
    ull d; asm("fma.rn.f32x2 %0,%1,%2,%3;" : "=l"(d) : "l"(a), "l"(b), "l"(c)); return d;
}
// middle pair {hi(a), lo(b)}
__device__ __forceinline__ ull mkmid(ull a, ull b) {
    float alo, ahi, blo, bhi;
    asm("mov.b64 {%0,%1},%2;" : "=f"(alo), "=f"(ahi) : "l"(a));
    asm("mov.b64 {%0,%1},%2;" : "=f"(blo), "=f"(bhi) : "l"(b));
    ull m; asm("mov.b64 %0,{%1,%2};" : "=l"(m) : "f"(ahi), "f"(blo));
    return m;
}

// =========================================================================
// P1: exp(conv_log_scale) interleaved with conv_bias + partial sums of cls
// =========================================================================
__global__ void prep_ecb(const float* __restrict__ cls, const float* __restrict__ cbias) {
    __shared__ float sred[256];
    int idx = blockIdx.x * 256 + threadIdx.x;   // 576*256 = 147456 exactly
    float v = cls[idx];
    g_ecb[2 * idx]     = expf(v);
    g_ecb[2 * idx + 1] = cbias[idx];
    sred[threadIdx.x] = v;
    __syncthreads();
    for (int s = 128; s > 0; s >>= 1) {
        if (threadIdx.x < s) sred[threadIdx.x] += sred[threadIdx.x + s];
        __syncthreads();
    }
    if (threadIdx.x == 0) g_cls_part[blockIdx.x] = sred[0];
}

// =========================================================================
// P2: fold actnorm into conv weights; alpha tables
// =========================================================================
__global__ void prep_w(const float* __restrict__ K, const float* __restrict__ als,
                       const float* __restrict__ ab, const float* __restrict__ sla) {
    int t = threadIdx.x;
    for (int i = t; i < LNUM * 108; i += 256) {
        int l = i / 108, r = i % 108;
        int o = r / 36, r2 = r % 36;
        int in = r2 / 12, tap = r2 % 12;
        float val = 0.f;
        if (tap < 9) {
            float a = expf(als[l * 3 + in]);
            val = K[((l * 3 + o) * 3 + in) * 9 + tap] * a;
        }
        g_Wp[i] = val;
    }
    for (int i = t; i < LNUM * 12; i += 256) {
        int l = i / 12, j = i % 12;
        float val = 0.f;
        if (j < 3) {
            float s = 0.f;
            for (int in = 0; in < 3; in++) {
                float ks = 0.f;
                for (int tap = 0; tap < 9; tap++)
                    ks += K[((l * 3 + j) * 3 + in) * 9 + tap];
                s += ab[l * 3 + in] * ks;
            }
            val = s;
        } else if (j < 6) {
            val = expf(sla[l * 3 + (j - 3)]);
        } else if (j < 9) {
            val = 1.0f / expf(sla[l * 3 + (j - 6)]);
        }
        g_aux[i] = val;
    }
}

// =========================================================================
// P3: spectral log|det| of circular conv operator
// =========================================================================
__global__ void kld_kernel(const float* __restrict__ K) {
    __shared__ float2 tw[128];
    __shared__ float sK[LNUM * 81];
    __shared__ float sred[256];
    int tid = threadIdx.x;
    if (tid < 128) {
        double a = -2.0 * 3.14159265358979323846 * (double)tid / 128.0;
        double s, c; sincos(a, &s, &c);
        tw[tid] = make_float2((float)c, (float)s);
    }
    if (tid < LNUM * 81) sK[tid] = K[tid];
    __syncthreads();

    int point = blockIdx.x * 256 + tid;  // 64*256 = 16384
    int u = point >> 7, v = point & 127;

    float res[LNUM];
    #pragma unroll
    for (int l = 0; l < LNUM; l++) {
        float er[9], ei[9];
        #pragma unroll
        for (int p = 0; p < 3; p++)
            #pragma unroll
            for (int q = 0; q < 3; q++) {
                int m = (u * p + v * q) & 127;
                float2 t = tw[m];
                er[p * 3 + q] = t.x; ei[p * 3 + q] = t.y;
            }
        float mr[3][3], mi[3][3];
        #pragma unroll
        for (int a = 0; a < 3; a++)
            #pragma unroll
            for (int b = 0; b < 3; b++) {
                float rr = 0.f, ri = 0.f;
                #pragma unroll
                for (int t = 0; t < 9; t++) {
                    float kk = sK[l * 81 + (a * 3 + b) * 9 + t];
                    rr += kk * er[t]; ri += kk * ei[t];
                }
                mr[a][b] = rr; mi[a][b] = ri;
            }
        float c0r = (mr[1][1]*mr[2][2] - mi[1][1]*mi[2][2]) - (mr[1][2]*mr[2][1] - mi[1][2]*mi[2][1]);
        float c0i = (mr[1][1]*mi[2][2] + mi[1][1]*mr[2][2]) - (mr[1][2]*mi[2][1] + mi[1][2]*mr[2][1]);
        float c1r = (mr[1][0]*mr[2][2] - mi[1][0]*mi[2][2]) - (mr[1][2]*mr[2][0] - mi[1][2]*mi[2][0]);
        float c1i = (mr[1][0]*mi[2][2] + mi[1][0]*mr[2][2]) - (mr[1][2]*mi[2][0] + mi[1][2]*mr[2][0]);
        float c2r = (mr[1][0]*mr[2][1] - mi[1][0]*mi[2][1]) - (mr[1][1]*mr[2][0] - mi[1][1]*mi[2][0]);
        float c2i = (mr[1][0]*mi[2][1] + mi[1][0]*mr[2][1]) - (mr[1][1]*mi[2][0] + mi[1][1]*mr[2][0]);
        float dr = (mr[0][0]*c0r - mi[0][0]*c0i) - (mr[0][1]*c1r - mi[0][1]*c1i) + (mr[0][2]*c2r - mi[0][2]*c2i);
        float di = (mr[0][0]*c0i + mi[0][0]*c0r) - (mr[0][1]*c1i + mi[0][1]*c1r) + (mr[0][2]*c2i + mi[0][2]*c2r);
        res[l] = 0.5f * logf(dr * dr + di * di);
    }

    for (int l = 0; l < LNUM; l++) {
        sred[tid] = res[l];
        __syncthreads();
        for (int s = 128; s > 0; s >>= 1) {
            if (tid < s) sred[tid] += sred[tid + s];
            __syncthreads();
        }
        if (tid == 0) g_kld_part[l * 64 + blockIdx.x] = sred[0];
        __syncthreads();
    }
}

// =========================================================================
// Main fused kernel: 3 layers, 32w x 16h tile, shrinking halos, f32x2.
// Buffers: pitch 40 floats. Stage dims (rows x cols): 20x36 -> 18x34 -> 16x32.
// =========================================================================
template <int DH_ROWS, int DW, bool LAST>
__device__ __forceinline__ float stage_p(const float* __restrict__ sin_, int pin,
                                         float* __restrict__ sout, int pout,
                                         float* __restrict__ gout,
                                         const ull* __restrict__ sWl,
                                         int layer, int ty0, int tx0, int off, int tid) {
    float4 a0 = __ldg((const float4*)&g_aux[layer * 12]);
    float4 a1 = __ldg((const float4*)&g_aux[layer * 12 + 4]);
    float4 a2 = __ldg((const float4*)&g_aux[layer * 12 + 8]);
    const float Bf[3]  = {a0.x, a0.y, a0.z};
    const float al[3]  = {a0.w, a1.x, a1.y};
    const float ial[3] = {a1.z, a1.w, a2.x};
    ull Bp[3];
    #pragma unroll
    for (int o = 0; o < 3; o++) Bp[o] = pk(Bf[o], Bf[o]);

    const float* __restrict__ ecb = g_ecb + layer * (C * NIMG * NIMG * 2);
    float acc_ld = 0.f;
    const int QH = DH_ROWS / 2;   // quad rows
    const int QW = DW / 2;        // quad cols
    const int NQ = QH * QW;

    #pragma unroll
    for (int q = tid; q < NQ; q += 128) {
        int qy = q / QW, qx = q - qy * QW;
        int py = qy * 2, px = qx * 2;

        ull acc2[2][3];
        #pragma unroll
        for (int R = 0; R < 2; R++)
            #pragma unroll
            for (int o = 0; o < 3; o++) acc2[R][o] = Bp[o];

        #pragma unroll
        for (int in = 0; in < 3; in++) {
            const float* bp = sin_ + in * pin + py * 40 + px;
            ull A[4], Bv[4], M[4];
            #pragma unroll
            for (int r = 0; r < 4; r++) {
                A[r]  = *(const ull*)(bp + r * 40);
                Bv[r] = *(const ull*)(bp + r * 40 + 2);
                M[r]  = mkmid(A[r], Bv[r]);
            }
            #pragma unroll
            for (int o = 0; o < 3; o++) {
                const ulonglong2* wb = (const ulonglong2*)(sWl + (in * 3 + o) * 10);
                ulonglong2 w01 = wb[0], w23 = wb[1], w45 = wb[2], w67 = wb[3], w8x = wb[4];
                ull wp[9] = {w01.x, w01.y, w23.x, w23.y, w45.x, w45.y, w67.x, w67.y, w8x.x};
                #pragma unroll
                for (int ty = 0; ty < 3; ty++) {
                    acc2[0][o] = f2fma(wp[ty * 3 + 0], A[ty],      acc2[0][o]);
                    acc2[0][o] = f2fma(wp[ty * 3 + 1], M[ty],      acc2[0][o]);
                    acc2[0][o] = f2fma(wp[ty * 3 + 2], Bv[ty],     acc2[0][o]);
                    acc2[1][o] = f2fma(wp[ty * 3 + 0], A[ty + 1],  acc2[1][o]);
                    acc2[1][o] = f2fma(wp[ty * 3 + 1], M[ty + 1],  acc2[1][o]);
                    acc2[1][o] = f2fma(wp[ty * 3 + 2], Bv[ty + 1], acc2[1][o]);
                }
            }
        }

        // epilogue: exp(cls)*conv + bias -> slog -> store + logdet accum
        #pragma unroll
        for (int R = 0; R < 2; R++) {
            int yloc = py + R - off;
            int gy = (ty0 + yloc) & 127;
            #pragma unroll
            for (int o = 0; o < 3; o++) {
                float c0, c1; upk(acc2[R][o], c0, c1);
                int xl0 = px - off;
                int gx0 = (tx0 + xl0) & 127;
                int gx1 = (tx0 + xl0 + 1) & 127;
                float2 e0 = *(const float2*)&ecb[((o * NIMG + gy) * NIMG + gx0) * 2];
                float2 e1 = *(const float2*)&ecb[((o * NIMG + gy) * NIMG + gx1) * 2];
                float u0 = fmaf(e0.x, c0, e0.y);
                float u1 = fmaf(e1.x, c1, e1.y);
                float w0 = ial[o] * __logf(fmaf(al[o], fabsf(u0), 1.0f));
                float w1 = ial[o] * __logf(fmaf(al[o], fabsf(u1), 1.0f));
                float h0 = copysignf(w0, u0);
                float h1 = copysignf(w1, u1);
                if (LAST || ((unsigned)yloc < 16u && (unsigned)xl0 < 32u))       acc_ld -= al[o] * w0;
                if (LAST || ((unsigned)yloc < 16u && (unsigned)(xl0 + 1) < 32u)) acc_ld -= al[o] * w1;
                if (!LAST) {
                    *(ull*)&sout[o * pout + (py + R) * 40 + px] = pk(h0, h1);
                } else {
                    *(float2*)(gout + ((size_t)o * NIMG + gy) * NIMG + (tx0 + px)) =
                        make_float2(h0, h1);
                }
            }
        }
    }
    return acc_ld;
}

__global__ void __launch_bounds__(128, 4) flow_main(const float* __restrict__ x,
                                                    float* __restrict__ out) {
    const int tid = threadIdx.x;
    const int b = blockIdx.x;        // batch-major: consecutive blocks share tile -> ecb L1 reuse
    const int tile = blockIdx.y;     // 0..31 : 4 x-tiles * 8 y-tiles
    const int tx0 = (tile & 3) * 32;
    const int ty0 = (tile >> 2) * 16;

    __shared__ __align__(16) float sA[3 * 22 * 40];   // input/stage buffer (22 rows max)
    __shared__ __align__(16) float sB[3 * 20 * 40];
    __shared__ __align__(16) ull sW[LNUM * 90];       // [l][in][o][10] duplicated pairs
    __shared__ float sred[128];

    // Build packed weight table
    for (int i = tid; i < LNUM * 90; i += 128) {
        int l = i / 90, r = i % 90;
        int in = r / 30, r2 = r % 30;
        int o = r2 / 10, tap = r2 % 10;
        float v = (tap < 9) ? g_Wp[((l * 3 + o) * 3 + in) * 12 + tap] : 0.f;
        sW[i] = pk(v, v);
    }

    // Load raw input tile (22 rows x 38 cols with wrap halo of 3)
    const float* __restrict__ xb = x + (size_t)b * (C * NIMG * NIMG);
    for (int i = tid; i < 3 * 22 * 38; i += 128) {
        int c = i / (22 * 38);
        int rem = i - c * (22 * 38);
        int r = rem / 38;
        int col = rem - r * 38;
        int gy = (ty0 + r - 3) & 127;
        int gx = (tx0 + col - 3) & 127;
        sA[c * (22 * 40) + r * 40 + col] = xb[(c * NIMG + gy) * NIMG + gx];
    }
    __syncthreads();

    float ldacc = 0.f;
    // layer 0: in sA(22 rows), out sB(20 rows x 36), off=2
    ldacc += stage_p<20, 36, false>(sA, 22 * 40, sB, 20 * 40, nullptr, sW + 0 * 90, 0, ty0, tx0, 2, tid);
    __syncthreads();
    // layer 1: in sB(20 rows), out sA(18 rows x 34), off=1
    ldacc += stage_p<18, 34, false>(sB, 20 * 40, sA, 18 * 40, nullptr, sW + 1 * 90, 1, ty0, tx0, 1, tid);
    __syncthreads();
    // layer 2: in sA(18 rows), out gmem (16 x 32), off=0
    ldacc += stage_p<16, 32, true>(sA, 18 * 40, nullptr, 0,
                                   out + (size_t)b * (C * NIMG * NIMG), sW + 2 * 90, 2, ty0, tx0, 0, tid);

    sred[tid] = ldacc;
    __syncthreads();
    for (int s = 64; s > 0; s >>= 1) {
        if (tid < s) sred[tid] += sred[tid + s];
        __syncthreads();
    }
    if (tid == 0) g_scratch[b * TILES + tile] = sred[0];
}

// =========================================================================
// F: per-batch logdet = scalar part + 32 tile partials (deterministic)
// =========================================================================
__global__ void final_ld(const float* __restrict__ als, float* __restrict__ out) {
    __shared__ float sred[256];
    int tid = threadIdx.x;
    float loc = 0.f;
    for (int i = tid; i < 576; i += 256) loc += g_cls_part[i];
    for (int i = tid; i < LNUM * 64; i += 256) loc += g_kld_part[i];
    sred[tid] = loc;
    __syncthreads();
    for (int s = 128; s > 0; s >>= 1) {
        if (tid < s) sred[tid] += sred[tid + s];
        __syncthreads();
    }
    if (tid == 0) {
        float s2 = 0.f;
        for (int i = 0; i < 9; i++) s2 += als[i];
        sred[0] = sred[0] + 16384.0f * s2;
    }
    __syncthreads();
    float scal = sred[0];
    int b = blockIdx.x * 256 + tid;
    if (b < BATCH) {
        float s = scal;
        #pragma unroll
        for (int t = 0; t < TILES; t++) s += g_scratch[b * TILES + t];
        out[H_ELEMS + b] = s;
    }
}

// =========================================================================
extern "C" void kernel_launch(void* const* d_in, const int* in_sizes, int n_in,
                              void* d_out, int out_size) {
    const float* x     = (const float*)d_in[0];
    const float* ab    = (const float*)d_in[1];
    const float* als   = (const float*)d_in[2];
    const float* K     = (const float*)d_in[3];
    const float* cbias = (const float*)d_in[4];
    const float* cls   = (const float*)d_in[5];
    const float* sla   = (const float*)d_in[6];
    float* out = (float*)d_out;

    prep_ecb<<<576, 256>>>(cls, cbias);
    prep_w<<<1, 256>>>(K, als, ab, sla);
    kld_kernel<<<64, 256>>>(K);
    flow_main<<<dim3(BATCH, TILES), 128>>>(x, out);   // our launch #4 (ncu target)
    final_ld<<<2, 256>>>(als, out);
}

// round 5
// speedup vs baseline: 1.5672x; 1.0085x over previous
#include <cuda_runtime.h>
#include <math.h>
#include <stdint.h>

typedef unsigned long long ull;

// Problem constants
#define BATCH 512
#define C 3
#define NIMG 128
#define LNUM 3
#define H_ELEMS (BATCH * C * NIMG * NIMG)   // 25165824
#define TILES 32                            // 4 x-tiles (32 wide) x 8 y-tiles (16 tall)
#define LN2F 0.69314718055994531f

// ---------------- device scratch (no allocations allowed) ----------------
__device__ __align__(16) float g_ecb[LNUM * C * NIMG * NIMG * 2]; // interleaved {exp(cls), conv_bias}
__device__ __align__(16) float g_Wp[LNUM * 3 * 3 * 12];           // folded conv weights, 12/(o,in)
__device__ __align__(16) float g_aux[LNUM * 12];                  // per layer: B[3], alpha[3], ln2/alpha[3]
__device__ float g_cls_part[576];
__device__ float g_kld_part[LNUM * 64];
__device__ float g_scratch[BATCH * TILES];

// ---------------- packed f32x2 helpers ----------------
__device__ __forceinline__ ull pk(float lo, float hi) {
    ull r; asm("mov.b64 %0,{%1,%2};" : "=l"(r) : "f"(lo), "f"(hi)); return r;
}
__device__ __forceinline__ void upk(ull p, float& lo, float& hi) {
    asm("mov.b64 {%0,%1},%2;" : "=f"(lo), "=f"(hi) : "l"(p));
}
__device__ __forceinline__ ull f2fma(ull a, ull b, ull c) {
    ull d; asm("fma.rn.f32x2 %0,%1,%2,%3;" : "=l"(d) : "l"(a), "l"(b), "l"(c)); return d;
}
// middle pair {hi(a), lo(b)}
__device__ __forceinline__ ull mkmid(ull a, ull b) {
    float alo, ahi, blo, bhi;
    asm("mov.b64 {%0,%1},%2;" : "=f"(alo), "=f"(ahi) : "l"(a));
    asm("mov.b64 {%0,%1},%2;" : "=f"(blo), "=f"(bhi) : "l"(b));
    ull m; asm("mov.b64 %0,{%1,%2};" : "=l"(m) : "f"(ahi), "f"(blo));
    return m;
}

// =========================================================================
// P1: exp(conv_log_scale) interleaved with conv_bias + partial sums of cls
// =========================================================================
__global__ void prep_ecb(const float* __restrict__ cls, const float* __restrict__ cbias) {
    __shared__ float sred[256];
    int idx = blockIdx.x * 256 + threadIdx.x;   // 576*256 = 147456 exactly
    float v = cls[idx];
    g_ecb[2 * idx]     = expf(v);
    g_ecb[2 * idx + 1] = cbias[idx];
    sred[threadIdx.x] = v;
    __syncthreads();
    for (int s = 128; s > 0; s >>= 1) {
        if (threadIdx.x < s) sred[threadIdx.x] += sred[threadIdx.x + s];
        __syncthreads();
    }
    if (threadIdx.x == 0) g_cls_part[blockIdx.x] = sred[0];
}

// =========================================================================
// P2: fold actnorm into conv weights; alpha tables
// =========================================================================
__global__ void prep_w(const float* __restrict__ K, const float* __restrict__ als,
                       const float* __restrict__ ab, const float* __restrict__ sla) {
    int t = threadIdx.x;
    for (int i = t; i < LNUM * 108; i += 256) {
        int l = i / 108, r = i % 108;
        int o = r / 36, r2 = r % 36;
        int in = r2 / 12, tap = r2 % 12;
        float val = 0.f;
        if (tap < 9) {
            float a = expf(als[l * 3 + in]);
            val = K[((l * 3 + o) * 3 + in) * 9 + tap] * a;
        }
        g_Wp[i] = val;
    }
    for (int i = t; i < LNUM * 12; i += 256) {
        int l = i / 12, j = i % 12;
        float val = 0.f;
        if (j < 3) {
            float s = 0.f;
            for (int in = 0; in < 3; in++) {
                float ks = 0.f;
                for (int tap = 0; tap < 9; tap++)
                    ks += K[((l * 3 + j) * 3 + in) * 9 + tap];
                s += ab[l * 3 + in] * ks;
            }
            val = s;
        } else if (j < 6) {
            val = expf(sla[l * 3 + (j - 3)]);
        } else if (j < 9) {
            val = LN2F / expf(sla[l * 3 + (j - 6)]);   // ln2/alpha
        }
        g_aux[i] = val;
    }
}

// =========================================================================
// P3: spectral log|det| of circular conv operator
// =========================================================================
__global__ void kld_kernel(const float* __restrict__ K) {
    __shared__ float2 tw[128];
    __shared__ float sK[LNUM * 81];
    __shared__ float sred[256];
    int tid = threadIdx.x;
    if (tid < 128) {
        double a = -2.0 * 3.14159265358979323846 * (double)tid / 128.0;
        double s, c; sincos(a, &s, &c);
        tw[tid] = make_float2((float)c, (float)s);
    }
    if (tid < LNUM * 81) sK[tid] = K[tid];
    __syncthreads();

    int point = blockIdx.x * 256 + tid;  // 64*256 = 16384
    int u = point >> 7, v = point & 127;

    float res[LNUM];
    #pragma unroll
    for (int l = 0; l < LNUM; l++) {
        float er[9], ei[9];
        #pragma unroll
        for (int p = 0; p < 3; p++)
            #pragma unroll
            for (int q = 0; q < 3; q++) {
                int m = (u * p + v * q) & 127;
                float2 t = tw[m];
                er[p * 3 + q] = t.x; ei[p * 3 + q] = t.y;
            }
        float mr[3][3], mi[3][3];
        #pragma unroll
        for (int a = 0; a < 3; a++)
            #pragma unroll
            for (int b = 0; b < 3; b++) {
                float rr = 0.f, ri = 0.f;
                #pragma unroll
                for (int t = 0; t < 9; t++) {
                    float kk = sK[l * 81 + (a * 3 + b) * 9 + t];
                    rr += kk * er[t]; ri += kk * ei[t];
                }
                mr[a][b] = rr; mi[a][b] = ri;
            }
        float c0r = (mr[1][1]*mr[2][2] - mi[1][1]*mi[2][2]) - (mr[1][2]*mr[2][1] - mi[1][2]*mi[2][1]);
        float c0i = (mr[1][1]*mi[2][2] + mi[1][1]*mr[2][2]) - (mr[1][2]*mi[2][1] + mi[1][2]*mr[2][1]);
        float c1r = (mr[1][0]*mr[2][2] - mi[1][0]*mi[2][2]) - (mr[1][2]*mr[2][0] - mi[1][2]*mi[2][0]);
        float c1i = (mr[1][0]*mi[2][2] + mi[1][0]*mr[2][2]) - (mr[1][2]*mi[2][0] + mi[1][2]*mr[2][0]);
        float c2r = (mr[1][0]*mr[2][1] - mi[1][0]*mi[2][1]) - (mr[1][1]*mr[2][0] - mi[1][1]*mi[2][0]);
        float c2i = (mr[1][0]*mi[2][1] + mi[1][0]*mr[2][1]) - (mr[1][1]*mi[2][0] + mi[1][1]*mr[2][0]);
        float dr = (mr[0][0]*c0r - mi[0][0]*c0i) - (mr[0][1]*c1r - mi[0][1]*c1i) + (mr[0][2]*c2r - mi[0][2]*c2i);
        float di = (mr[0][0]*c0i + mi[0][0]*c0r) - (mr[0][1]*c1i + mi[0][1]*c1r) + (mr[0][2]*c2i + mi[0][2]*c2r);
        res[l] = 0.5f * logf(dr * dr + di * di);
    }

    for (int l = 0; l < LNUM; l++) {
        sred[tid] = res[l];
        __syncthreads();
        for (int s = 128; s > 0; s >>= 1) {
            if (tid < s) sred[tid] += sred[tid + s];
            __syncthreads();
        }
        if (tid == 0) g_kld_part[l * 64 + blockIdx.x] = sred[0];
        __syncthreads();
    }
}

// =========================================================================
// One 2x2 quad of one stage. Returns sum of lg2(1 + a|u|) over counted px.
// =========================================================================
template <int QW, bool LAST, int OFF>
__device__ __forceinline__ float do_quad(int q,
                                         const float* __restrict__ sin_, int pin,
                                         float* __restrict__ sout, int pout,
                                         float* __restrict__ gout,
                                         const ull* __restrict__ sWl,
                                         const float* __restrict__ ecb,
                                         const ull* Bp, const float* al, const float* ial2,
                                         int ty0, int tx0) {
    int qy = q / QW, qx = q - qy * QW;
    int py = qy * 2, px = qx * 2;

    // ---- prefetch epilogue scale/bias pairs (latency hidden by conv) ----
    int xl0 = px - OFF, yl0 = py - OFF;
    int gy0 = (ty0 + yl0) & 127;
    int gy1 = (ty0 + yl0 + 1) & 127;
    int gx0 = (tx0 + xl0) & 127;
    int gx1 = (tx0 + xl0 + 1) & 127;
    float2 e[2][3][2];
    #pragma unroll
    for (int o = 0; o < 3; o++) {
        e[0][o][0] = *(const float2*)&ecb[((o * NIMG + gy0) * NIMG + gx0) * 2];
        e[0][o][1] = *(const float2*)&ecb[((o * NIMG + gy0) * NIMG + gx1) * 2];
        e[1][o][0] = *(const float2*)&ecb[((o * NIMG + gy1) * NIMG + gx0) * 2];
        e[1][o][1] = *(const float2*)&ecb[((o * NIMG + gy1) * NIMG + gx1) * 2];
    }

    ull acc2[2][3];
    #pragma unroll
    for (int R = 0; R < 2; R++)
        #pragma unroll
        for (int o = 0; o < 3; o++) acc2[R][o] = Bp[o];

    #pragma unroll
    for (int in = 0; in < 3; in++) {
        const float* bp = sin_ + in * pin + py * 40 + px;
        ull A[4], Bv[4], M[4];
        #pragma unroll
        for (int r = 0; r < 4; r++) {
            A[r]  = *(const ull*)(bp + r * 40);
            Bv[r] = *(const ull*)(bp + r * 40 + 2);
            M[r]  = mkmid(A[r], Bv[r]);
        }
        #pragma unroll
        for (int o = 0; o < 3; o++) {
            const ulonglong2* wb = (const ulonglong2*)(sWl + (in * 3 + o) * 10);
            ulonglong2 w01 = wb[0], w23 = wb[1], w45 = wb[2], w67 = wb[3], w8x = wb[4];
            ull wp[9] = {w01.x, w01.y, w23.x, w23.y, w45.x, w45.y, w67.x, w67.y, w8x.x};
            #pragma unroll
            for (int ty = 0; ty < 3; ty++) {
                acc2[0][o] = f2fma(wp[ty * 3 + 0], A[ty],      acc2[0][o]);
                acc2[0][o] = f2fma(wp[ty * 3 + 1], M[ty],      acc2[0][o]);
                acc2[0][o] = f2fma(wp[ty * 3 + 2], Bv[ty],     acc2[0][o]);
                acc2[1][o] = f2fma(wp[ty * 3 + 0], A[ty + 1],  acc2[1][o]);
                acc2[1][o] = f2fma(wp[ty * 3 + 1], M[ty + 1],  acc2[1][o]);
                acc2[1][o] = f2fma(wp[ty * 3 + 2], Bv[ty + 1], acc2[1][o]);
            }
        }
    }

    // ---- epilogue ----
    float lg2sum = 0.f;
    #pragma unroll
    for (int R = 0; R < 2; R++) {
        int yloc = py + R - OFF;
        int gy = R ? gy1 : gy0;
        #pragma unroll
        for (int o = 0; o < 3; o++) {
            float c0, c1; upk(acc2[R][o], c0, c1);
            float2 e0 = e[R][o][0], e1 = e[R][o][1];
            float u0 = fmaf(e0.x, c0, e0.y);
            float u1 = fmaf(e1.x, c1, e1.y);
            float g0 = __log2f(fmaf(al[o], fabsf(u0), 1.0f));   // lg2(1 + a|u|)
            float g1 = __log2f(fmaf(al[o], fabsf(u1), 1.0f));
            float h0 = copysignf(ial2[o] * g0, u0);             // (ln2/a)*lg2 = log1p/a
            float h1 = copysignf(ial2[o] * g1, u1);
            if (LAST || ((unsigned)yloc < 16u && (unsigned)xl0 < 32u))       lg2sum += g0;
            if (LAST || ((unsigned)yloc < 16u && (unsigned)(xl0 + 1) < 32u)) lg2sum += g1;
            if (!LAST) {
                *(ull*)&sout[o * pout + (py + R) * 40 + px] = pk(h0, h1);
            } else {
                *(float2*)(gout + ((size_t)o * NIMG + gy) * NIMG + (tx0 + px)) =
                    make_float2(h0, h1);
            }
        }
    }
    return lg2sum;
}

// =========================================================================
// One stage: quad loop has exactly <=2 iterations; unrolled explicitly.
// =========================================================================
template <int DH_ROWS, int DW, bool LAST, int OFF>
__device__ __forceinline__ float stage_p(const float* __restrict__ sin_, int pin,
                                         float* __restrict__ sout, int pout,
                                         float* __restrict__ gout,
                                         const ull* __restrict__ sWl,
                                         int layer, int ty0, int tx0, int tid) {
    float4 a0 = __ldg((const float4*)&g_aux[layer * 12]);
    float4 a1 = __ldg((const float4*)&g_aux[layer * 12 + 4]);
    float4 a2 = __ldg((const float4*)&g_aux[layer * 12 + 8]);
    const float al[3]   = {a0.w, a1.x, a1.y};
    const float ial2[3] = {a1.z, a1.w, a2.x};   // ln2/alpha
    ull Bp[3] = {pk(a0.x, a0.x), pk(a0.y, a0.y), pk(a0.z, a0.z)};

    const float* __restrict__ ecb = g_ecb + layer * (C * NIMG * NIMG * 2);
    constexpr int QH = DH_ROWS / 2;
    constexpr int QW = DW / 2;
    constexpr int NQ = QH * QW;   // 180 / 153 / 128

    float s = do_quad<QW, LAST, OFF>(tid, sin_, pin, sout, pout, gout, sWl, ecb,
                                     Bp, al, ial2, ty0, tx0);
    if constexpr (NQ > 128) {
        if (tid < NQ - 128)
            s += do_quad<QW, LAST, OFF>(tid + 128, sin_, pin, sout, pout, gout, sWl, ecb,
                                        Bp, al, ial2, ty0, tx0);
    }
    return s;
}

__global__ void __launch_bounds__(128, 6) flow_main(const float* __restrict__ x,
                                                    float* __restrict__ out) {
    const int tid = threadIdx.x;
    const int b = blockIdx.x;        // batch-major: consecutive blocks share tile -> ecb reuse
    const int tile = blockIdx.y;     // 0..31 : 4 x-tiles * 8 y-tiles
    const int tx0 = (tile & 3) * 32;
    const int ty0 = (tile >> 2) * 16;

    __shared__ __align__(16) float sA[3 * 22 * 40];
    __shared__ __align__(16) float sB[3 * 20 * 40];
    __shared__ __align__(16) ull sW[LNUM * 90];
    __shared__ float sred[128];

    // Build packed weight table
    for (int i = tid; i < LNUM * 90; i += 128) {
        int l = i / 90, r = i % 90;
        int in = r / 30, r2 = r % 30;
        int o = r2 / 10, tap = r2 % 10;
        float v = (tap < 9) ? g_Wp[((l * 3 + o) * 3 + in) * 12 + tap] : 0.f;
        sW[i] = pk(v, v);
    }

    // Load raw input tile (22 rows x 38 cols, wrap halo of 3)
    const float* __restrict__ xb = x + (size_t)b * (C * NIMG * NIMG);
    for (int i = tid; i < 3 * 22 * 38; i += 128) {
        int c = i / (22 * 38);
        int rem = i - c * (22 * 38);
        int r = rem / 38;
        int col = rem - r * 38;
        int gy = (ty0 + r - 3) & 127;
        int gx = (tx0 + col - 3) & 127;
        sA[c * (22 * 40) + r * 40 + col] = xb[(c * NIMG + gy) * NIMG + gx];
    }
    __syncthreads();

    float lg2acc = 0.f;
    lg2acc += stage_p<20, 36, false, 2>(sA, 22 * 40, sB, 20 * 40, nullptr, sW + 0 * 90, 0, ty0, tx0, tid);
    __syncthreads();
    lg2acc += stage_p<18, 34, false, 1>(sB, 20 * 40, sA, 18 * 40, nullptr, sW + 1 * 90, 1, ty0, tx0, tid);
    __syncthreads();
    lg2acc += stage_p<16, 32, true, 0>(sA, 18 * 40, nullptr, 0,
                                       out + (size_t)b * (C * NIMG * NIMG), sW + 2 * 90, 2, ty0, tx0, tid);

    sred[tid] = lg2acc;
    __syncthreads();
    for (int s = 64; s > 0; s >>= 1) {
        if (tid < s) sred[tid] += sred[tid + s];
        __syncthreads();
    }
    if (tid == 0) g_scratch[b * TILES + tile] = -LN2F * sred[0];
}

// =========================================================================
// F: per-batch logdet = scalar part + 32 tile partials (deterministic)
// =========================================================================
__global__ void final_ld(const float* __restrict__ als, float* __restrict__ out) {
    __shared__ float sred[256];
    int tid = threadIdx.x;
    float loc = 0.f;
    for (int i = tid; i < 576; i += 256) loc += g_cls_part[i];
    for (int i = tid; i < LNUM * 64; i += 256) loc += g_kld_part[i];
    sred[tid] = loc;
    __syncthreads();
    for (int s = 128; s > 0; s >>= 1) {
        if (tid < s) sred[tid] += sred[tid + s];
        __syncthreads();
    }
    if (tid == 0) {
        float s2 = 0.f;
        for (int i = 0; i < 9; i++) s2 += als[i];
        sred[0] = sred[0] + 16384.0f * s2;
    }
    __syncthreads();
    float scal = sred[0];
    int b = blockIdx.x * 256 + tid;
    if (b < BATCH) {
        float s = scal;
        #pragma unroll
        for (int t = 0; t < TILES; t++) s += g_scratch[b * TILES + t];
        out[H_ELEMS + b] = s;
    }
}

// =========================================================================
extern "C" void kernel_launch(void* const* d_in, const int* in_sizes, int n_in,
                              void* d_out, int out_size) {
    const float* x     = (const float*)d_in[0];
    const float* ab    = (const float*)d_in[1];
    const float* als   = (const float*)d_in[2];
    const float* K     = (const float*)d_in[3];
    const float* cbias = (const float*)d_in[4];
    const float* cls   = (const float*)d_in[5];
    const float* sla   = (const float*)d_in[6];
    float* out = (float*)d_out;

    prep_ecb<<<576, 256>>>(cls, cbias);
    prep_w<<<1, 256>>>(K, als, ab, sla);
    kld_kernel<<<64, 256>>>(K);
    flow_main<<<dim3(BATCH, TILES), 128>>>(x, out);   // our launch #4 (ncu target)
    final_ld<<<2, 256>>>(als, out);
}